// round 3
// baseline (speedup 1.0000x reference)
#include <cuda_runtime.h>
#include <cuda_bf16.h>
#include <math.h>
#include <stdint.h>

// Problem constants:
// B=512, L=128, DIM=100, PDIM=25, WIN=3, FEAT=350, FNUM=256, LAB=19
// conv GEMM: M=512*128, N=256, K=3*350, computed as 3 taps x K=350
// bf16 split: C = Ah*Bh + Ah*Bl + Al*Bh  (9 passes of K=352-padded)

#define BF16 __nv_bfloat16

// ---------------- scratch (static device arrays; no allocations allowed) ----
__device__ BF16  g_Rh[512 * 130 * 352];   // padded R rows (352-wide), bf16 hi
__device__ BF16  g_Rl[512 * 130 * 352];   // bf16 lo residual
__device__ BF16  g_Wh[3 * 352 * 256];     // W[t][k][f] bf16 hi (k padded to 352)
__device__ BF16  g_Wl[3 * 352 * 256];     // bf16 lo
__device__ float g_Rc[512 * 128 * 256];   // tanh(conv+bias), fp32
__device__ float g_T [512 * 128 * 19];    // T = Rc . U

static __device__ __forceinline__ uint32_t smem_u32(const void* p) {
    uint32_t r;
    asm("{ .reg .u64 t; cvta.to.shared.u64 t, %1; cvt.u32.u64 %0, t; }" : "=r"(r) : "l"(p));
    return r;
}
static __device__ __forceinline__ void cp16(uint32_t dst, const void* src) {
    asm volatile("cp.async.cg.shared.global [%0], [%1], 16;" :: "r"(dst), "l"(src));
}
static __device__ __forceinline__ void mma_bf16(float* c, const uint32_t* a, uint32_t b0, uint32_t b1) {
    asm volatile(
        "mma.sync.aligned.m16n8k16.row.col.f32.bf16.bf16.f32 "
        "{%0,%1,%2,%3}, {%4,%5,%6,%7}, {%8,%9}, {%0,%1,%2,%3};"
        : "+f"(c[0]), "+f"(c[1]), "+f"(c[2]), "+f"(c[3])
        : "r"(a[0]), "r"(a[1]), "r"(a[2]), "r"(a[3]), "r"(b0), "r"(b1));
}

// ---------------------------------------------------------------------------
// Kernel A: gather embeddings, span means, dual softmax attention, build R
// writes bf16 hi/lo padded-row buffers. one block per b, 256 threads.
// ---------------------------------------------------------------------------
__global__ void prep_kernel(const int* __restrict__ inputs,
                            const int* __restrict__ e1s_, const int* __restrict__ e1e_,
                            const int* __restrict__ e2s_, const int* __restrict__ e2e_,
                            const int* __restrict__ p1, const int* __restrict__ p2,
                            const float* __restrict__ emb,
                            const float* __restrict__ pos1, const float* __restrict__ pos2)
{
    extern __shared__ float sm[];
    float* we   = sm;                   // [128][101]
    float* emb0 = sm + 12928;
    float* l1   = emb0 + 100;
    float* l2   = l1 + 100;
    float* sc1  = l2 + 100;
    float* sc2  = sc1 + 128;
    float* ine  = sc2 + 128;
    int*   ids  = (int*)(ine + 128);
    int*   q1   = ids + 128;
    int*   q2   = q1 + 128;
    __shared__ float m1s, S1s, m2s, S2s;

    const int b = blockIdx.x;
    const int tid = threadIdx.x;

    if (tid < 128) {
        ids[tid] = inputs[b * 128 + tid];
        q1[tid]  = p1[b * 128 + tid];
        q2[tid]  = p2[b * 128 + tid];
    } else if (tid < 228) {
        emb0[tid - 128] = emb[tid - 128];   // emb row 0 (pad token)
    }
    __syncthreads();

    for (int i = tid; i < 128 * 100; i += 256) {
        int l = i / 100;
        int d = i - l * 100;
        we[l * 101 + d] = emb[(long long)ids[l] * 100 + d];
    }
    __syncthreads();

    if (tid < 100) {
        int s1i = e1s_[b], e1i = e1e_[b];
        int s2i = e2s_[b], e2i = e2e_[b];
        float a = 0.f, c = 0.f;
        for (int l = s1i; l <= e1i; ++l) a += we[l * 101 + tid];
        for (int l = s2i; l <= e2i; ++l) c += we[l * 101 + tid];
        l1[tid] = a / (float)(e1i - s1i + 1);
        l2[tid] = c / (float)(e2i - s2i + 1);
    }
    __syncthreads();

    if (tid < 128) {
        float a = 0.f, c = 0.f;
        const float* w = we + tid * 101;
        #pragma unroll 4
        for (int d = 0; d < 100; ++d) { a += w[d] * l1[d]; c += w[d] * l2[d]; }
        sc1[tid] = a; sc2[tid] = c;
    }
    __syncthreads();

    if (tid < 64) {
        const float* sc = (tid < 32) ? sc1 : sc2;
        int lane = tid & 31;
        float m = -1e30f;
        for (int l = lane; l < 128; l += 32) m = fmaxf(m, sc[l]);
        for (int o = 16; o; o >>= 1) m = fmaxf(m, __shfl_xor_sync(0xffffffffu, m, o));
        float s = 0.f;
        for (int l = lane; l < 128; l += 32) s += expf(sc[l] - m);
        for (int o = 16; o; o >>= 1) s += __shfl_xor_sync(0xffffffffu, s, o);
        if (lane == 0) {
            if (tid < 32) { m1s = m; S1s = s; } else { m2s = m; S2s = s; }
        }
    }
    __syncthreads();

    if (tid < 128)
        ine[tid] = 0.5f * (expf(sc1[tid] - m1s) / S1s + expf(sc2[tid] - m2s) / S2s);
    __syncthreads();

    // write R rows (padded row l+1), cols 0..351 (350,351 zero), bf16 hi/lo
    BF16* rh = g_Rh + ((size_t)b * 130 + 1) * 352;
    BF16* rl = g_Rl + ((size_t)b * 130 + 1) * 352;
    for (int i = tid; i < 128 * 352; i += 256) {
        int l = i / 352;
        int d = i - l * 352;
        float v = 0.f;
        if (d < 350) {
            float s = ine[l];
            if (d < 300) {
                if (l != 0) {
                    int j = d / 100;
                    int dd = d - j * 100;
                    int lw = l - 1 + j;           // 0..128
                    v = ((lw < 128) ? we[lw * 101 + dd] : emb0[dd]) * s;
                }
            } else if (d < 325) {
                v = pos1[q1[l] * 25 + (d - 300)] * s;
            } else {
                v = pos2[q2[l] * 25 + (d - 325)] * s;
            }
        }
        BF16 hi = __float2bfloat16(v);
        BF16 lo = __float2bfloat16(v - __bfloat162float(hi));
        rh[(size_t)l * 352 + d] = hi;
        rl[(size_t)l * 352 + d] = lo;
    }
    // zero padding rows 0 and 129
    for (int d = tid; d < 352; d += 256) {
        BF16 z = __float2bfloat16(0.f);
        g_Rh[((size_t)b * 130) * 352 + d] = z;
        g_Rh[((size_t)b * 130 + 129) * 352 + d] = z;
        g_Rl[((size_t)b * 130) * 352 + d] = z;
        g_Rl[((size_t)b * 130 + 129) * 352 + d] = z;
    }
}

// ---------------------------------------------------------------------------
// Kernel W: split conv weights into bf16 hi/lo, layout [t][k(352)][f(256)]
// ---------------------------------------------------------------------------
__global__ void wsplit_kernel(const float* __restrict__ convw)
{
    int kk = blockIdx.x;      // 0..1055 = t*352 + k
    int f  = threadIdx.x;     // 0..255
    int t  = kk / 352;
    int k  = kk - t * 352;
    float v = (k < 350) ? convw[(size_t)f * 1050 + t * 350 + k] : 0.f;
    BF16 hi = __float2bfloat16(v);
    BF16 lo = __float2bfloat16(v - __bfloat162float(hi));
    g_Wh[(size_t)kk * 256 + f] = hi;
    g_Wl[(size_t)kk * 256 + f] = lo;
}

// ---------------------------------------------------------------------------
// Kernel B: conv as bf16x3 tensor-core GEMM + bias + tanh
// Block tile 128(M) x 128(N), BK=32, 256 threads = 8 warps (4m x 2n),
// warp tile 32x64, mma.sync m16n8k16. 9 passes x 11 chunks = 99 iters.
// ---------------------------------------------------------------------------
__device__ __forceinline__ void conv_load(int q, int b, int n0, BF16 (*As)[40], BF16 (*Bs)[136], int tid)
{
    int pass = q / 11, ch = q - pass * 11;
    int t = pass / 3, sp = pass - t * 3;
    const BF16* Ap = (sp < 2 ? g_Rh : g_Rl) + ((size_t)(b * 130 + t)) * 352 + ch * 32;
    const BF16* Bp = (sp == 1 ? g_Wl : g_Wh) + ((size_t)(t * 352 + ch * 32)) * 256 + n0;
    int am = tid >> 1, ah = (tid & 1) * 16;               // A: 128 rows x 32 cols
    cp16(smem_u32(&As[am][ah]),     Ap + (size_t)am * 352 + ah);
    cp16(smem_u32(&As[am][ah + 8]), Ap + (size_t)am * 352 + ah + 8);
    int bk = tid >> 3, bs = (tid & 7) * 16;               // B: 32 rows x 128 cols
    cp16(smem_u32(&Bs[bk][bs]),     Bp + (size_t)bk * 256 + bs);
    cp16(smem_u32(&Bs[bk][bs + 8]), Bp + (size_t)bk * 256 + bs + 8);
}

__global__ __launch_bounds__(256, 2) void conv_mma_kernel(const float* __restrict__ convb)
{
    __shared__ BF16 As[2][128][40];   // rows padded to 80B: conflict-free ldmatrix
    __shared__ BF16 Bs[2][32][136];   // rows padded to 272B

    const int b   = blockIdx.y;
    const int n0  = blockIdx.x * 128;
    const int tid = threadIdx.x;
    const int lane = tid & 31;
    const int wid  = tid >> 5;
    const int wm = wid >> 1;          // 0..3
    const int wn = wid & 1;           // 0..1

    float acc[2][8][4];
    #pragma unroll
    for (int s = 0; s < 2; ++s)
        #pragma unroll
        for (int j = 0; j < 8; ++j)
            #pragma unroll
            for (int x = 0; x < 4; ++x) acc[s][j][x] = 0.f;

    conv_load(0, b, n0, As[0], Bs[0], tid);
    asm volatile("cp.async.commit_group;");

    for (int q = 0; q < 99; ++q) {
        asm volatile("cp.async.wait_group 0;");
        __syncthreads();
        if (q + 1 < 99) {
            conv_load(q + 1, b, n0, As[(q + 1) & 1], Bs[(q + 1) & 1], tid);
            asm volatile("cp.async.commit_group;");
        }
        BF16 (*A)[40]  = As[q & 1];
        BF16 (*Bb)[136] = Bs[q & 1];

        #pragma unroll
        for (int ks = 0; ks < 2; ++ks) {
            uint32_t a[2][4];
            #pragma unroll
            for (int s = 0; s < 2; ++s) {
                uint32_t addr = smem_u32(&A[wm * 32 + s * 16 + (lane & 15)][ks * 16 + (lane >> 4) * 8]);
                asm volatile("ldmatrix.sync.aligned.m8n8.x4.shared.b16 {%0,%1,%2,%3}, [%4];"
                             : "=r"(a[s][0]), "=r"(a[s][1]), "=r"(a[s][2]), "=r"(a[s][3]) : "r"(addr));
            }
            #pragma unroll
            for (int i = 0; i < 4; ++i) {
                uint32_t bb[4];
                uint32_t addr = smem_u32(&Bb[ks * 16 + (lane & 7) + ((lane >> 3) & 1) * 8]
                                           [wn * 64 + i * 16 + (lane >> 4) * 8]);
                asm volatile("ldmatrix.sync.aligned.m8n8.x4.trans.shared.b16 {%0,%1,%2,%3}, [%4];"
                             : "=r"(bb[0]), "=r"(bb[1]), "=r"(bb[2]), "=r"(bb[3]) : "r"(addr));
                #pragma unroll
                for (int s = 0; s < 2; ++s) {
                    mma_bf16(acc[s][2 * i],     a[s], bb[0], bb[1]);
                    mma_bf16(acc[s][2 * i + 1], a[s], bb[2], bb[3]);
                }
            }
        }
        __syncthreads();
    }

    // epilogue: bias + tanh -> g_Rc fp32
    const int col_base = n0 + wn * 64 + (lane & 3) * 2;
    float bias[8][2];
    #pragma unroll
    for (int j = 0; j < 8; ++j) {
        bias[j][0] = __ldg(convb + col_base + j * 8);
        bias[j][1] = __ldg(convb + col_base + j * 8 + 1);
    }
    #pragma unroll
    for (int s = 0; s < 2; ++s) {
        int row = b * 128 + wm * 32 + s * 16 + (lane >> 2);
        #pragma unroll
        for (int j = 0; j < 8; ++j) {
            int col = col_base + j * 8;
            g_Rc[(size_t)row * 256 + col]            = tanhf(acc[s][j][0] + bias[j][0]);
            g_Rc[(size_t)row * 256 + col + 1]        = tanhf(acc[s][j][1] + bias[j][1]);
            g_Rc[(size_t)(row + 8) * 256 + col]      = tanhf(acc[s][j][2] + bias[j][0]);
            g_Rc[(size_t)(row + 8) * 256 + col + 1]  = tanhf(acc[s][j][3] + bias[j][1]);
        }
    }
}

// ---------------------------------------------------------------------------
// Kernel C1: T[b][l][c] = sum_f Rc[b][l][f] * U[f][c]
// warp handles 4 rows (l); lanes split f; shfl reduce. grid (4, 512) x 256.
// ---------------------------------------------------------------------------
__global__ __launch_bounds__(256) void t_kernel(const float* __restrict__ U)
{
    __shared__ float Us[4864];
    const int tid = threadIdx.x;
    for (int i = tid; i < 4864; i += 256) Us[i] = U[i];
    __syncthreads();

    const int lane = tid & 31, w = tid >> 5;
    const int b = blockIdx.y;
    const int l0 = blockIdx.x * 32 + w * 4;
    const float* rc = g_Rc + ((size_t)b * 128 + l0) * 256;

    float acc[4][19];
    #pragma unroll
    for (int j = 0; j < 4; ++j)
        #pragma unroll
        for (int c = 0; c < 19; ++c) acc[j][c] = 0.f;

    for (int r = 0; r < 8; ++r) {
        int f = lane + 32 * r;
        float a0 = rc[f];
        float a1 = rc[256 + f];
        float a2 = rc[512 + f];
        float a3 = rc[768 + f];
        const float* up = Us + f * 19;
        #pragma unroll
        for (int c = 0; c < 19; ++c) {
            float u = up[c];
            acc[0][c] += a0 * u;
            acc[1][c] += a1 * u;
            acc[2][c] += a2 * u;
            acc[3][c] += a3 * u;
        }
    }
    #pragma unroll
    for (int j = 0; j < 4; ++j)
        #pragma unroll
        for (int c = 0; c < 19; ++c) {
            float v = acc[j][c];
            #pragma unroll
            for (int o = 16; o; o >>= 1) v += __shfl_xor_sync(0xffffffffu, v, o);
            if (lane == c) g_T[((size_t)b * 128 + l0 + j) * 19 + c] = v;
        }
}

// ---------------------------------------------------------------------------
// Kernel C2: G = T.WL, online softmax over l, wo[g] = max_l Rc*softG
// block per b, thread per g, T broadcast from smem. Single pass over l.
// ---------------------------------------------------------------------------
__global__ __launch_bounds__(256) void head2_kernel(const float* __restrict__ WL,
                                                    float* __restrict__ out)
{
    __shared__ float Ts[128 * 20];
    const int tid = threadIdx.x, b = blockIdx.x;
    const float* tg = g_T + (size_t)b * 128 * 19;
    for (int i = tid; i < 2432; i += 256) {
        int l = i / 19, c = i - l * 19;
        Ts[l * 20 + c] = tg[i];
    }
    __syncthreads();

    const int g = tid;
    float wl[19];
    #pragma unroll
    for (int c = 0; c < 19; ++c) wl[c] = WL[c * 256 + g];

    const float* rcg = g_Rc + (size_t)b * 128 * 256 + g;

    // seed with l = 0
    float m = 0.f;
    #pragma unroll
    for (int c = 0; c < 19; ++c) m += Ts[c] * wl[c];
    float S = 1.f;
    float vmax = rcg[0];

    for (int l = 1; l < 128; ++l) {
        const float* tl = Ts + l * 20;
        float g2 = 0.f;
        #pragma unroll
        for (int c = 0; c < 19; ++c) g2 += tl[c] * wl[c];
        float rc = rcg[(size_t)l * 256];
        float m2 = fmaxf(m, g2);
        float c1 = __expf(m - m2);
        float c2 = __expf(g2 - m2);
        S = S * c1 + c2;
        vmax = fmaxf(vmax * c1, rc * c2);
        m = m2;
    }
    out[(size_t)b * 256 + g] = vmax / S;
}

// ---------------------------------------------------------------------------
__global__ void wl_copy_kernel(const float* __restrict__ WL, float* __restrict__ out)
{
    int i = blockIdx.x * 256 + threadIdx.x;
    if (i < 19 * 256) out[512 * 256 + i] = WL[i];
}

// ---------------------------------------------------------------------------
extern "C" void kernel_launch(void* const* d_in, const int* in_sizes, int n_in,
                              void* d_out, int out_size)
{
    const int*   inputs = (const int*)d_in[0];
    const int*   e1s    = (const int*)d_in[1];
    const int*   e1e    = (const int*)d_in[2];
    const int*   e2s    = (const int*)d_in[3];
    const int*   e2e    = (const int*)d_in[4];
    const int*   p1     = (const int*)d_in[5];
    const int*   p2     = (const int*)d_in[6];
    const float* emb    = (const float*)d_in[7];
    const float* pos1   = (const float*)d_in[8];
    const float* pos2   = (const float*)d_in[9];
    const float* convw  = (const float*)d_in[10];
    const float* convb  = (const float*)d_in[11];
    const float* U      = (const float*)d_in[12];
    const float* WL     = (const float*)d_in[13];
    float* out = (float*)d_out;

    const int PREP_SMEM = 13996 * 4;    // 55984 B
    cudaFuncSetAttribute(prep_kernel, cudaFuncAttributeMaxDynamicSharedMemorySize, PREP_SMEM);

    prep_kernel<<<512, 256, PREP_SMEM>>>(inputs, e1s, e1e, e2s, e2e, p1, p2, emb, pos1, pos2);
    wsplit_kernel<<<1056, 256>>>(convw);
    conv_mma_kernel<<<dim3(2, 512), 256>>>(convb);
    t_kernel<<<dim3(4, 512), 256>>>(U);
    head2_kernel<<<512, 256>>>(WL, out);
    wl_copy_kernel<<<19, 256>>>(WL, out);
}

// round 6
// speedup vs baseline: 1.1202x; 1.1202x over previous
#include <cuda_runtime.h>
#include <cuda_bf16.h>
#include <math.h>
#include <stdint.h>

#define BF16 __nv_bfloat16

// ---------------- scratch ----------------
__device__ BF16  g_Rh[512 * 130 * 352];   // padded R rows, bf16 hi
__device__ BF16  g_Rl[512 * 130 * 352];   // bf16 lo residual
__device__ BF16  g_Wh[3 * 352 * 256];     // W[t][k][f] bf16 hi
__device__ BF16  g_Wl[3 * 352 * 256];     // bf16 lo
__device__ float g_Rc[512 * 128 * 256];
__device__ float g_T [512 * 128 * 19];

static __device__ __forceinline__ uint32_t smem_u32(const void* p) {
    uint32_t r;
    asm("{ .reg .u64 t; cvta.to.shared.u64 t, %1; cvt.u32.u64 %0, t; }" : "=r"(r) : "l"(p));
    return r;
}
static __device__ __forceinline__ void cp16(uint32_t dst, const void* src) {
    asm volatile("cp.async.cg.shared.global [%0], [%1], 16;" :: "r"(dst), "l"(src));
}
static __device__ __forceinline__ void mma_bf16(float* c, const uint32_t* a, uint32_t b0, uint32_t b1) {
    asm volatile(
        "mma.sync.aligned.m16n8k16.row.col.f32.bf16.bf16.f32 "
        "{%0,%1,%2,%3}, {%4,%5,%6,%7}, {%8,%9}, {%0,%1,%2,%3};"
        : "+f"(c[0]), "+f"(c[1]), "+f"(c[2]), "+f"(c[3])
        : "r"(a[0]), "r"(a[1]), "r"(a[2]), "r"(a[3]), "r"(b0), "r"(b1));
}

// ---------------------------------------------------------------------------
// Kernel A: gather, span means, dual softmax, write bf16 hi/lo R (352-wide)
// (unchanged from the passing round-2 kernel)
// ---------------------------------------------------------------------------
__global__ void prep_kernel(const int* __restrict__ inputs,
                            const int* __restrict__ e1s_, const int* __restrict__ e1e_,
                            const int* __restrict__ e2s_, const int* __restrict__ e2e_,
                            const int* __restrict__ p1, const int* __restrict__ p2,
                            const float* __restrict__ emb,
                            const float* __restrict__ pos1, const float* __restrict__ pos2)
{
    extern __shared__ float smf[];
    float* we   = smf;                  // [128][101]
    float* emb0 = smf + 12928;
    float* l1   = emb0 + 100;
    float* l2   = l1 + 100;
    float* sc1  = l2 + 100;
    float* sc2  = sc1 + 128;
    float* ine  = sc2 + 128;
    int*   ids  = (int*)(ine + 128);
    int*   q1   = ids + 128;
    int*   q2   = q1 + 128;
    __shared__ float m1s, S1s, m2s, S2s;

    const int b = blockIdx.x;
    const int tid = threadIdx.x;

    if (tid < 128) {
        ids[tid] = inputs[b * 128 + tid];
        q1[tid]  = p1[b * 128 + tid];
        q2[tid]  = p2[b * 128 + tid];
    } else if (tid < 228) {
        emb0[tid - 128] = emb[tid - 128];
    }
    __syncthreads();

    for (int i = tid; i < 128 * 100; i += 256) {
        int l = i / 100, d = i - l * 100;
        we[l * 101 + d] = emb[(long long)ids[l] * 100 + d];
    }
    __syncthreads();

    if (tid < 100) {
        int s1i = e1s_[b], e1i = e1e_[b];
        int s2i = e2s_[b], e2i = e2e_[b];
        float a = 0.f, c = 0.f;
        for (int l = s1i; l <= e1i; ++l) a += we[l * 101 + tid];
        for (int l = s2i; l <= e2i; ++l) c += we[l * 101 + tid];
        l1[tid] = a / (float)(e1i - s1i + 1);
        l2[tid] = c / (float)(e2i - s2i + 1);
    }
    __syncthreads();

    if (tid < 128) {
        float a = 0.f, c = 0.f;
        const float* w = we + tid * 101;
        #pragma unroll 4
        for (int d = 0; d < 100; ++d) { a += w[d] * l1[d]; c += w[d] * l2[d]; }
        sc1[tid] = a; sc2[tid] = c;
    }
    __syncthreads();

    if (tid < 64) {
        const float* sc = (tid < 32) ? sc1 : sc2;
        int lane = tid & 31;
        float m = -1e30f;
        for (int l = lane; l < 128; l += 32) m = fmaxf(m, sc[l]);
        for (int o = 16; o; o >>= 1) m = fmaxf(m, __shfl_xor_sync(0xffffffffu, m, o));
        float s = 0.f;
        for (int l = lane; l < 128; l += 32) s += expf(sc[l] - m);
        for (int o = 16; o; o >>= 1) s += __shfl_xor_sync(0xffffffffu, s, o);
        if (lane == 0) {
            if (tid < 32) { m1s = m; S1s = s; } else { m2s = m; S2s = s; }
        }
    }
    __syncthreads();

    if (tid < 128)
        ine[tid] = 0.5f * (expf(sc1[tid] - m1s) / S1s + expf(sc2[tid] - m2s) / S2s);
    __syncthreads();

    BF16* rh = g_Rh + ((size_t)b * 130 + 1) * 352;
    BF16* rl = g_Rl + ((size_t)b * 130 + 1) * 352;
    for (int i = tid; i < 128 * 352; i += 256) {
        int l = i / 352, d = i - l * 352;
        float v = 0.f;
        if (d < 350) {
            float s = ine[l];
            if (d < 300) {
                if (l != 0) {
                    int j = d / 100, dd = d - j * 100;
                    int lw = l - 1 + j;
                    v = ((lw < 128) ? we[lw * 101 + dd] : emb0[dd]) * s;
                }
            } else if (d < 325) {
                v = pos1[q1[l] * 25 + (d - 300)] * s;
            } else {
                v = pos2[q2[l] * 25 + (d - 325)] * s;
            }
        }
        BF16 hi = __float2bfloat16(v);
        BF16 lo = __float2bfloat16(v - __bfloat162float(hi));
        rh[(size_t)l * 352 + d] = hi;
        rl[(size_t)l * 352 + d] = lo;
    }
    for (int d = tid; d < 352; d += 256) {
        BF16 z = __float2bfloat16(0.f);
        g_Rh[((size_t)b * 130) * 352 + d] = z;
        g_Rh[((size_t)b * 130 + 129) * 352 + d] = z;
        g_Rl[((size_t)b * 130) * 352 + d] = z;
        g_Rl[((size_t)b * 130 + 129) * 352 + d] = z;
    }
}

// ---------------------------------------------------------------------------
// Kernel W: split conv weights -> [t][k(352)][f(256)] bf16 hi/lo
// ---------------------------------------------------------------------------
__global__ void wsplit_kernel(const float* __restrict__ convw)
{
    int kk = blockIdx.x;      // 0..1055 = t*352 + k
    int f  = threadIdx.x;     // 0..255
    int t  = kk / 352;
    int k  = kk - t * 352;
    float v = (k < 350) ? convw[(size_t)f * 1050 + t * 350 + k] : 0.f;
    BF16 hi = __float2bfloat16(v);
    BF16 lo = __float2bfloat16(v - __bfloat162float(hi));
    g_Wh[(size_t)kk * 256 + f] = hi;
    g_Wl[(size_t)kk * 256 + f] = lo;
}

// ---------------------------------------------------------------------------
// Kernel B: conv as bf16x3 tensor-core GEMM, merged 3-pass chunks.
// One CTA per b: M=128, N=256, 512 thr = 16 warps (4m x 4n), warp tile 32x64.
// 33 chunks (3 taps x 11 k-slices of 32); each chunk does AhBh + AlBh + AhBl.
// Dynamic smem double buffer: per buf: Ah 10240, Al 10240, B rows 528B:
//   Bh 16896, Bl 16896 -> 54272 B; x2 = 108544 B.
// ---------------------------------------------------------------------------
#define ABUF 54272
#define AH_OFF 0
#define AL_OFF 10240
#define BH_OFF 20480
#define BL_OFF 37376

static __device__ __forceinline__ void conv_load(uint32_t smb, int q, int b, int tid)
{
    const int t = q / 11, kc = q - t * 11;
    const uint32_t d = smb + (q & 1) * ABUF;
    // A: 128 rows x 32 k (hi+lo). thread: row=tid>>2, col=(tid&3)*8
    {
        int am = tid >> 2, ac = (tid & 3) * 8;
        size_t src = ((size_t)(b * 130 + t + am)) * 352 + kc * 32 + ac;
        uint32_t dst = d + am * 80 + ac * 2;
        cp16(dst + AH_OFF, g_Rh + src);
        cp16(dst + AL_OFF, g_Rl + src);
    }
    // B: 32 k x 256 n (hi+lo). thread: k=tid>>4, nseg=(tid&15)*16
    {
        int bk = tid >> 4, bn = (tid & 15) * 16;
        size_t src = ((size_t)(t * 352 + kc * 32 + bk)) * 256 + bn;
        uint32_t dst = d + bk * 528 + bn * 2;
        cp16(dst + BH_OFF,      g_Wh + src);
        cp16(dst + BH_OFF + 16, g_Wh + src + 8);
        cp16(dst + BL_OFF,      g_Wl + src);
        cp16(dst + BL_OFF + 16, g_Wl + src + 8);
    }
}

__global__ __launch_bounds__(512, 1) void conv_mma_kernel(const float* __restrict__ convb)
{
    extern __shared__ __align__(256) char smc[];
    const uint32_t smb = smem_u32(smc);
    const int tid = threadIdx.x;
    const int lane = tid & 31;
    const int wid  = tid >> 5;
    const int wm = wid & 3;           // 0..3 (m)
    const int wn = wid >> 2;          // 0..3 (n)
    const int b  = blockIdx.x;

    float acc[2][8][4];
    #pragma unroll
    for (int s = 0; s < 2; ++s)
        #pragma unroll
        for (int j = 0; j < 8; ++j)
            #pragma unroll
            for (int x = 0; x < 4; ++x) acc[s][j][x] = 0.f;

    conv_load(smb, 0, b, tid);
    asm volatile("cp.async.commit_group;" ::: "memory");

    // precomputed ldmatrix addresses (per-chunk add buffer offset)
    const uint32_t aAddrBase = smb + (wm * 32 + (lane & 15)) * 80 + (lane >> 4) * 16;
    const uint32_t bAddrBase = smb + ((lane & 7) + ((lane >> 3) & 1) * 8) * 528
                                   + (wn * 64 + (lane >> 4) * 8) * 2;

    for (int q = 0; q < 33; ++q) {
        asm volatile("cp.async.wait_group 0;" ::: "memory");
        __syncthreads();
        if (q + 1 < 33) {
            conv_load(smb, q + 1, b, tid);
            asm volatile("cp.async.commit_group;" ::: "memory");
        }
        const uint32_t d = (q & 1) * ABUF;

        #pragma unroll
        for (int ks = 0; ks < 2; ++ks) {
            uint32_t ah[2][4], al[2][4];
            #pragma unroll
            for (int s = 0; s < 2; ++s) {
                uint32_t addr = aAddrBase + d + (s * 16) * 80 + ks * 32;
                asm volatile("ldmatrix.sync.aligned.m8n8.x4.shared.b16 {%0,%1,%2,%3}, [%4];"
                             : "=r"(ah[s][0]), "=r"(ah[s][1]), "=r"(ah[s][2]), "=r"(ah[s][3])
                             : "r"(addr + AH_OFF));
                asm volatile("ldmatrix.sync.aligned.m8n8.x4.shared.b16 {%0,%1,%2,%3}, [%4];"
                             : "=r"(al[s][0]), "=r"(al[s][1]), "=r"(al[s][2]), "=r"(al[s][3])
                             : "r"(addr + AL_OFF));
            }
            #pragma unroll
            for (int i = 0; i < 4; ++i) {
                uint32_t bb[4];
                uint32_t addr = bAddrBase + d + (ks * 16) * 528 + i * 32;
                asm volatile("ldmatrix.sync.aligned.m8n8.x4.trans.shared.b16 {%0,%1,%2,%3}, [%4];"
                             : "=r"(bb[0]), "=r"(bb[1]), "=r"(bb[2]), "=r"(bb[3])
                             : "r"(addr + BH_OFF));
                #pragma unroll
                for (int s = 0; s < 2; ++s) {
                    mma_bf16(acc[s][2 * i],     ah[s], bb[0], bb[1]);
                    mma_bf16(acc[s][2 * i + 1], ah[s], bb[2], bb[3]);
                    mma_bf16(acc[s][2 * i],     al[s], bb[0], bb[1]);
                    mma_bf16(acc[s][2 * i + 1], al[s], bb[2], bb[3]);
                }
                asm volatile("ldmatrix.sync.aligned.m8n8.x4.trans.shared.b16 {%0,%1,%2,%3}, [%4];"
                             : "=r"(bb[0]), "=r"(bb[1]), "=r"(bb[2]), "=r"(bb[3])
                             : "r"(addr + BL_OFF));
                #pragma unroll
                for (int s = 0; s < 2; ++s) {
                    mma_bf16(acc[s][2 * i],     ah[s], bb[0], bb[1]);
                    mma_bf16(acc[s][2 * i + 1], ah[s], bb[2], bb[3]);
                }
            }
        }
        __syncthreads();
    }

    // epilogue: bias + tanh -> g_Rc fp32
    const int col_base = wn * 64 + (lane & 3) * 2;
    float bias[8][2];
    #pragma unroll
    for (int j = 0; j < 8; ++j) {
        bias[j][0] = __ldg(convb + col_base + j * 8);
        bias[j][1] = __ldg(convb + col_base + j * 8 + 1);
    }
    #pragma unroll
    for (int s = 0; s < 2; ++s) {
        int row = b * 128 + wm * 32 + s * 16 + (lane >> 2);
        #pragma unroll
        for (int j = 0; j < 8; ++j) {
            int col = col_base + j * 8;
            g_Rc[(size_t)row * 256 + col]           = tanhf(acc[s][j][0] + bias[j][0]);
            g_Rc[(size_t)row * 256 + col + 1]       = tanhf(acc[s][j][1] + bias[j][1]);
            g_Rc[(size_t)(row + 8) * 256 + col]     = tanhf(acc[s][j][2] + bias[j][0]);
            g_Rc[(size_t)(row + 8) * 256 + col + 1] = tanhf(acc[s][j][3] + bias[j][1]);
        }
    }
}

// ---------------------------------------------------------------------------
// Kernel C1: T[b][l][c] = sum_f Rc[b][l][f] * U[f][c]; warp per row.
// grid (16, 512), block 256 (8 warps).
// ---------------------------------------------------------------------------
__global__ __launch_bounds__(256) void t_kernel(const float* __restrict__ U)
{
    __shared__ float Us[4864];
    const int tid = threadIdx.x;
    for (int i = tid; i < 4864; i += 256) Us[i] = U[i];
    __syncthreads();

    const int lane = tid & 31, w = tid >> 5;
    const int b = blockIdx.y;
    const int l = blockIdx.x * 8 + w;
    const float* rc = g_Rc + ((size_t)b * 128 + l) * 256;

    float acc[19];
    #pragma unroll
    for (int c = 0; c < 19; ++c) acc[c] = 0.f;

    #pragma unroll
    for (int r = 0; r < 8; ++r) {
        int f = r * 32 + lane;
        float a = rc[f];
        const float* up = Us + f * 19;
        #pragma unroll
        for (int c = 0; c < 19; ++c) acc[c] += a * up[c];
    }
    #pragma unroll
    for (int c = 0; c < 19; ++c) {
        float v = acc[c];
        #pragma unroll
        for (int o = 16; o; o >>= 1) v += __shfl_xor_sync(0xffffffffu, v, o);
        if (lane == c) g_T[((size_t)b * 128 + l) * 19 + c] = v;
    }
}

// ---------------------------------------------------------------------------
// Kernel C2: G = T.WL, online softmax over l, wo = max_l Rc * softG
// ---------------------------------------------------------------------------
__global__ __launch_bounds__(256) void head2_kernel(const float* __restrict__ WL,
                                                    float* __restrict__ out)
{
    __shared__ float Ts[128 * 20];
    const int tid = threadIdx.x, b = blockIdx.x;
    const float* tg = g_T + (size_t)b * 128 * 19;
    for (int i = tid; i < 2432; i += 256) {
        int l = i / 19, c = i - l * 19;
        Ts[l * 20 + c] = tg[i];
    }
    __syncthreads();

    const int g = tid;
    float wl[19];
    #pragma unroll
    for (int c = 0; c < 19; ++c) wl[c] = WL[c * 256 + g];

    const float* rcg = g_Rc + (size_t)b * 128 * 256 + g;
    float m = 0.f;
    #pragma unroll
    for (int c = 0; c < 19; ++c) m += Ts[c] * wl[c];
    float S = 1.f;
    float vmax = rcg[0];
    for (int l = 1; l < 128; ++l) {
        const float* tl = Ts + l * 20;
        float g2 = 0.f;
        #pragma unroll
        for (int c = 0; c < 19; ++c) g2 += tl[c] * wl[c];
        float rc = rcg[(size_t)l * 256];
        float m2 = fmaxf(m, g2);
        float c1 = __expf(m - m2), c2 = __expf(g2 - m2);
        S = S * c1 + c2;
        vmax = fmaxf(vmax * c1, rc * c2);
        m = m2;
    }
    out[(size_t)b * 256 + g] = vmax / S;
}

__global__ void wl_copy_kernel(const float* __restrict__ WL, float* __restrict__ out)
{
    int i = blockIdx.x * 256 + threadIdx.x;
    if (i < 19 * 256) out[512 * 256 + i] = WL[i];
}

// ---------------------------------------------------------------------------
extern "C" void kernel_launch(void* const* d_in, const int* in_sizes, int n_in,
                              void* d_out, int out_size)
{
    const int*   inputs = (const int*)d_in[0];
    const int*   e1s    = (const int*)d_in[1];
    const int*   e1e    = (const int*)d_in[2];
    const int*   e2s    = (const int*)d_in[3];
    const int*   e2e    = (const int*)d_in[4];
    const int*   p1     = (const int*)d_in[5];
    const int*   p2     = (const int*)d_in[6];
    const float* emb    = (const float*)d_in[7];
    const float* pos1   = (const float*)d_in[8];
    const float* pos2   = (const float*)d_in[9];
    const float* convw  = (const float*)d_in[10];
    const float* convb  = (const float*)d_in[11];
    const float* U      = (const float*)d_in[12];
    const float* WL     = (const float*)d_in[13];
    float* out = (float*)d_out;

    const int PREP_SMEM = 13996 * 4;
    const int CONV_SMEM = 2 * ABUF;   // 108544
    cudaFuncSetAttribute(prep_kernel, cudaFuncAttributeMaxDynamicSharedMemorySize, PREP_SMEM);
    cudaFuncSetAttribute(conv_mma_kernel, cudaFuncAttributeMaxDynamicSharedMemorySize, CONV_SMEM);

    prep_kernel<<<512, 256, PREP_SMEM>>>(inputs, e1s, e1e, e2s, e2e, p1, p2, emb, pos1, pos2);
    wsplit_kernel<<<1056, 256>>>(convw);
    conv_mma_kernel<<<512, 512, CONV_SMEM>>>(convb);
    t_kernel<<<dim3(16, 512), 256>>>(U);
    head2_kernel<<<512, 256>>>(WL, out);
    wl_copy_kernel<<<19, 256>>>(WL, out);
}